// round 4
// baseline (speedup 1.0000x reference)
#include <cuda_runtime.h>
#include <cuda_bf16.h>

// Problem shape (fixed):
//   decoder_hidden  Q : [32, 512, 512]  f32
//   encoder_outputs E : [32, 2048, 512] f32  (acts as K and V)
//   out             O : [32, 512, 512]  f32
//
// Pipeline: S = Q @ E^T  -> softmax rows -> O = P @ E

#define BATCH 32
#define TQ    512
#define TK    2048
#define DIM   512

#define BM 128
#define BN 128
#define BK 16
#define TM 8
#define TN 8

// 128 MiB scratch for the score / probability matrix (allowed: __device__ global)
__device__ float g_scores[(size_t)BATCH * TQ * TK];

// ---------------------------------------------------------------------------
// f32x2 helpers (Blackwell packed-fp32 FMA: 2x the 3-reg FFMA rate)
// ---------------------------------------------------------------------------
__device__ __forceinline__ unsigned long long ffma2(unsigned long long a,
                                                    unsigned long long b,
                                                    unsigned long long c) {
    unsigned long long d;
    asm("fma.rn.f32x2 %0, %1, %2, %3;" : "=l"(d) : "l"(a), "l"(b), "l"(c));
    return d;
}

__device__ __forceinline__ unsigned long long dup2(float x) {
    unsigned long long d;
    unsigned int xi = __float_as_uint(x);
    asm("mov.b64 %0, {%1, %1};" : "=l"(d) : "r"(xi));
    return d;
}

// ---------------------------------------------------------------------------
// Tiled GEMM:  C[m][n] = sum_k A[m][k] * B'[k][n]
//   A: row-major M x K (k contiguous)   -- always
//   BT = true : B is row-major N x K (k contiguous), i.e. C = A @ B^T  (QK^T)
//   BT = false: B is row-major K x N (n contiguous), i.e. C = A @ B    (P @ V)
// 128x128 CTA tile, BK=16 double-buffered, 256 threads, 8x8 micro-tile
// computed as 8 x (4 f32x2 pairs).
// ---------------------------------------------------------------------------
template <bool BT>
__global__ void __launch_bounds__(256, 1)
gemm_kernel(const float* __restrict__ A, const float* __restrict__ B,
            float* __restrict__ C,
            int M, int N, int Kd, int lda, int ldb, int ldc,
            long long sA, long long sB, long long sC)
{
    __shared__ __align__(16) float As[2][BK][BM + 4];
    __shared__ __align__(16) float Bs[2][BK][BN + 4];

    const int bz = blockIdx.z;
    A += (long long)bz * sA;
    B += (long long)bz * sB;
    C += (long long)bz * sC;

    const int m0  = blockIdx.y * BM;
    const int n0  = blockIdx.x * BN;
    const int tid = threadIdx.x;

    // A tile (BM x BK), transposed into As[k][m]: each thread loads 2 float4
    const int ar = tid >> 2;          // 0..63  (+64 for second row group)
    const int ac = (tid & 3) << 2;    // 0,4,8,12 (k offset)

    // B tile
    // BT: (BN x BK) transposed into Bs[k][n], same pattern as A
    // !BT: (BK x BN) copied row-wise into Bs[k][n]
    const int br = BT ? (tid >> 2) : (tid >> 4);        // BT: 0..63  !BT: 0..15
    const int bc = BT ? ((tid & 3) << 2) : ((tid & 15) << 2); // BT: k off !BT: n off

    const int tx = tid & 15;   // n group: columns tx*8 .. tx*8+7
    const int ty = tid >> 4;   // m group: rows    ty*8 .. ty*8+7

    unsigned long long acc[TM][TN / 2];
#pragma unroll
    for (int i = 0; i < TM; i++)
#pragma unroll
        for (int j = 0; j < TN / 2; j++) acc[i][j] = 0ull;

    const int nk = Kd / BK;

    float4 aR0, aR1, bR0, bR1;

    // ---- prologue: load tile 0 into buffer 0 ----
    {
        const float* Ap = A + (long long)(m0 + ar) * lda + ac;
        aR0 = *(const float4*)Ap;
        aR1 = *(const float4*)(Ap + (long long)64 * lda);
        if (BT) {
            const float* Bp = B + (long long)(n0 + br) * ldb + bc;
            bR0 = *(const float4*)Bp;
            bR1 = *(const float4*)(Bp + (long long)64 * ldb);
        } else {
            const float* Bp = B + (long long)br * ldb + n0 + bc;
            bR0 = *(const float4*)Bp;
            bR1 = *(const float4*)(Bp + 64);
        }
        As[0][ac + 0][ar]      = aR0.x;
        As[0][ac + 1][ar]      = aR0.y;
        As[0][ac + 2][ar]      = aR0.z;
        As[0][ac + 3][ar]      = aR0.w;
        As[0][ac + 0][ar + 64] = aR1.x;
        As[0][ac + 1][ar + 64] = aR1.y;
        As[0][ac + 2][ar + 64] = aR1.z;
        As[0][ac + 3][ar + 64] = aR1.w;
        if (BT) {
            Bs[0][bc + 0][br]      = bR0.x;
            Bs[0][bc + 1][br]      = bR0.y;
            Bs[0][bc + 2][br]      = bR0.z;
            Bs[0][bc + 3][br]      = bR0.w;
            Bs[0][bc + 0][br + 64] = bR1.x;
            Bs[0][bc + 1][br + 64] = bR1.y;
            Bs[0][bc + 2][br + 64] = bR1.z;
            Bs[0][bc + 3][br + 64] = bR1.w;
        } else {
            *(float4*)&Bs[0][br][bc]      = bR0;
            *(float4*)&Bs[0][br][bc + 64] = bR1;
        }
    }
    __syncthreads();

    int cur = 0;
    for (int kt = 0; kt < nk; kt++) {
        const int k1 = (kt + 1) * BK;
        const bool has_next = (kt + 1 < nk);

        // ---- prefetch next tile into registers ----
        if (has_next) {
            const float* Ap = A + (long long)(m0 + ar) * lda + k1 + ac;
            aR0 = *(const float4*)Ap;
            aR1 = *(const float4*)(Ap + (long long)64 * lda);
            if (BT) {
                const float* Bp = B + (long long)(n0 + br) * ldb + k1 + bc;
                bR0 = *(const float4*)Bp;
                bR1 = *(const float4*)(Bp + (long long)64 * ldb);
            } else {
                const float* Bp = B + (long long)(k1 + br) * ldb + n0 + bc;
                bR0 = *(const float4*)Bp;
                bR1 = *(const float4*)(Bp + 64);
            }
        }

        // ---- compute on current buffer ----
#pragma unroll
        for (int kk = 0; kk < BK; kk++) {
            const ulonglong2 bq0 = *(const ulonglong2*)&Bs[cur][kk][tx * TN];
            const ulonglong2 bq1 = *(const ulonglong2*)&Bs[cur][kk][tx * TN + 4];
            const float4 a0 = *(const float4*)&As[cur][kk][ty * TM];
            const float4 a1 = *(const float4*)&As[cur][kk][ty * TM + 4];
            unsigned long long ap[TM];
            ap[0] = dup2(a0.x); ap[1] = dup2(a0.y);
            ap[2] = dup2(a0.z); ap[3] = dup2(a0.w);
            ap[4] = dup2(a1.x); ap[5] = dup2(a1.y);
            ap[6] = dup2(a1.z); ap[7] = dup2(a1.w);
            const unsigned long long bp[4] = {bq0.x, bq0.y, bq1.x, bq1.y};
#pragma unroll
            for (int i = 0; i < TM; i++)
#pragma unroll
                for (int j = 0; j < 4; j++)
                    acc[i][j] = ffma2(ap[i], bp[j], acc[i][j]);
        }

        // ---- store prefetched tile into the other buffer ----
        if (has_next) {
            const int nxt = cur ^ 1;
            As[nxt][ac + 0][ar]      = aR0.x;
            As[nxt][ac + 1][ar]      = aR0.y;
            As[nxt][ac + 2][ar]      = aR0.z;
            As[nxt][ac + 3][ar]      = aR0.w;
            As[nxt][ac + 0][ar + 64] = aR1.x;
            As[nxt][ac + 1][ar + 64] = aR1.y;
            As[nxt][ac + 2][ar + 64] = aR1.z;
            As[nxt][ac + 3][ar + 64] = aR1.w;
            if (BT) {
                Bs[nxt][bc + 0][br]      = bR0.x;
                Bs[nxt][bc + 1][br]      = bR0.y;
                Bs[nxt][bc + 2][br]      = bR0.z;
                Bs[nxt][bc + 3][br]      = bR0.w;
                Bs[nxt][bc + 0][br + 64] = bR1.x;
                Bs[nxt][bc + 1][br + 64] = bR1.y;
                Bs[nxt][bc + 2][br + 64] = bR1.z;
                Bs[nxt][bc + 3][br + 64] = bR1.w;
            } else {
                *(float4*)&Bs[nxt][br][bc]      = bR0;
                *(float4*)&Bs[nxt][br][bc + 64] = bR1;
            }
        }
        __syncthreads();
        cur ^= 1;
    }

    // ---- epilogue: each acc pair is (col n, col n+1) little-endian ----
#pragma unroll
    for (int i = 0; i < TM; i++) {
        float* Cp = C + (long long)(m0 + ty * TM + i) * ldc + n0 + tx * TN;
#pragma unroll
        for (int j = 0; j < 4; j++)
            *reinterpret_cast<unsigned long long*>(Cp + 2 * j) = acc[i][j];
    }
}

// ---------------------------------------------------------------------------
// Row softmax over 2048 elements, one block (256 threads) per row, in place.
// ---------------------------------------------------------------------------
__global__ void __launch_bounds__(256, 4)
softmax2048_kernel(float* __restrict__ S)
{
    __shared__ float red[8];
    __shared__ float red2[8];

    const long long row = blockIdx.x;
    float* p = S + row * (long long)TK;
    const int tid = threadIdx.x;

    float4 v0 = *(float4*)(p + tid * 4);
    float4 v1 = *(float4*)(p + 1024 + tid * 4);

    float m = fmaxf(fmaxf(fmaxf(v0.x, v0.y), fmaxf(v0.z, v0.w)),
                    fmaxf(fmaxf(v1.x, v1.y), fmaxf(v1.z, v1.w)));
#pragma unroll
    for (int o = 16; o > 0; o >>= 1)
        m = fmaxf(m, __shfl_xor_sync(0xffffffffu, m, o));
    if ((tid & 31) == 0) red[tid >> 5] = m;
    __syncthreads();
    m = fmaxf(fmaxf(fmaxf(red[0], red[1]), fmaxf(red[2], red[3])),
              fmaxf(fmaxf(red[4], red[5]), fmaxf(red[6], red[7])));

    float e[8];
    e[0] = __expf(v0.x - m); e[1] = __expf(v0.y - m);
    e[2] = __expf(v0.z - m); e[3] = __expf(v0.w - m);
    e[4] = __expf(v1.x - m); e[5] = __expf(v1.y - m);
    e[6] = __expf(v1.z - m); e[7] = __expf(v1.w - m);

    float s = ((e[0] + e[1]) + (e[2] + e[3])) + ((e[4] + e[5]) + (e[6] + e[7]));
#pragma unroll
    for (int o = 16; o > 0; o >>= 1)
        s += __shfl_xor_sync(0xffffffffu, s, o);
    if ((tid & 31) == 0) red2[tid >> 5] = s;
    __syncthreads();
    s = ((red2[0] + red2[1]) + (red2[2] + red2[3])) +
        ((red2[4] + red2[5]) + (red2[6] + red2[7]));

    const float inv = 1.0f / s;
    v0.x = e[0] * inv; v0.y = e[1] * inv; v0.z = e[2] * inv; v0.w = e[3] * inv;
    v1.x = e[4] * inv; v1.y = e[5] * inv; v1.z = e[6] * inv; v1.w = e[7] * inv;

    *(float4*)(p + tid * 4)        = v0;
    *(float4*)(p + 1024 + tid * 4) = v1;
}

// ---------------------------------------------------------------------------
// Entry point
// ---------------------------------------------------------------------------
extern "C" void kernel_launch(void* const* d_in, const int* in_sizes, int n_in,
                              void* d_out, int out_size)
{
    const float* Q = (const float*)d_in[0];  // [32, 512, 512]
    const float* E = (const float*)d_in[1];  // [32, 2048, 512]
    float* O = (float*)d_out;                // [32, 512, 512]

    float* S = nullptr;
    cudaGetSymbolAddress((void**)&S, g_scores);

    dim3 blk(256);

    // S = Q @ E^T : M=512, N=2048, K=512
    gemm_kernel<true><<<dim3(TK / BN, TQ / BM, BATCH), blk>>>(
        Q, E, S,
        TQ, TK, DIM,
        DIM, DIM, TK,
        (long long)TQ * DIM, (long long)TK * DIM, (long long)TQ * TK);

    // row softmax over TK
    softmax2048_kernel<<<BATCH * TQ, 256>>>(S);

    // O = P @ E : M=512, N=512, K=2048
    gemm_kernel<false><<<dim3(DIM / BN, TQ / BM, BATCH), blk>>>(
        S, E, O,
        TQ, DIM, TK,
        TK, DIM, DIM,
        (long long)TQ * TK, (long long)TK * DIM, (long long)TQ * DIM);
}

// round 10
// speedup vs baseline: 1.9156x; 1.9156x over previous
#include <cuda_runtime.h>
#include <cuda_bf16.h>

typedef unsigned int       u32;
typedef unsigned long long u64;

#define BATCH 32
#define TQ    512
#define TK    2048
#define DIM   512

#define K1 (3 * DIM)   // 1536  (split-K for GEMM1)
#define K2 (3 * TK)    // 6144  (split-K for GEMM2)

// ---------------------------------------------------------------------------
// Scratch (device globals: allocation-free per harness rules)
// ---------------------------------------------------------------------------
__device__ __nv_bfloat16 g_Q3 [(size_t)BATCH * TQ  * K1];   //  50 MB
__device__ __nv_bfloat16 g_E3 [(size_t)BATCH * TK  * K1];   // 201 MB
__device__ float         g_S  [(size_t)BATCH * TQ  * TK];   // 134 MB
__device__ __nv_bfloat16 g_P3 [(size_t)BATCH * TQ  * K2];   // 201 MB
__device__ __nv_bfloat16 g_ET3[(size_t)BATCH * DIM * K2];   // 201 MB

// ---------------------------------------------------------------------------
// Baseline-PTX tensor-core helpers (no tcgen05 — sm_103 generic target)
// ---------------------------------------------------------------------------
__device__ __forceinline__ u32 smem_u32(const void* p) {
    u32 a;
    asm("{ .reg .u64 t; cvta.to.shared.u64 t, %1; cvt.u32.u64 %0, t; }"
        : "=r"(a) : "l"(p));
    return a;
}

__device__ __forceinline__ void ldmatrix_x4(u32& r0, u32& r1, u32& r2, u32& r3,
                                            u32 addr) {
    asm volatile("ldmatrix.sync.aligned.m8n8.x4.shared.b16 {%0,%1,%2,%3}, [%4];"
                 : "=r"(r0), "=r"(r1), "=r"(r2), "=r"(r3) : "r"(addr));
}

__device__ __forceinline__ void mma_16816(float* c, const u32* a, const u32* b) {
    asm volatile(
        "mma.sync.aligned.m16n8k16.row.col.f32.bf16.bf16.f32 "
        "{%0,%1,%2,%3}, {%4,%5,%6,%7}, {%8,%9}, {%0,%1,%2,%3};"
        : "+f"(c[0]), "+f"(c[1]), "+f"(c[2]), "+f"(c[3])
        : "r"(a[0]), "r"(a[1]), "r"(a[2]), "r"(a[3]), "r"(b[0]), "r"(b[1]));
}

#define CP_ASYNC_16(saddr, gptr) \
    asm volatile("cp.async.cg.shared.global [%0], [%1], 16;" \
                 :: "r"(saddr), "l"(gptr) : "memory")
#define CP_COMMIT() asm volatile("cp.async.commit_group;" ::: "memory")
#define CP_WAIT(n)  asm volatile("cp.async.wait_group %0;" :: "n"(n) : "memory")

// ---------------------------------------------------------------------------
// Tiled NT GEMM on tensor cores: C[m][n] = sum_k A[m][k] * B[n][k]
//   A: [M, KTOT] bf16 k-contiguous, B: [N, KTOT] bf16 k-contiguous, C f32.
// CTA 128x128, BK=32, 4-stage cp.async pipeline, 8 warps (32x64 warp tiles).
// smem rows padded to 40 bf16 (80B): conflict-free ldmatrix at stride 80.
// ---------------------------------------------------------------------------
#define STAGES   4
#define ROWPAD   40                          // 32 data + 8 pad bf16
#define TILE_B   (128 * ROWPAD * 2)          // 10240 bytes per A or B tile
#define STAGE_B  (2 * TILE_B)                // 20480
#define GEMM_SMEM (STAGES * STAGE_B)         // 81920

template <int KTOT>
__global__ void __launch_bounds__(256, 2)
gemm_mma(const __nv_bfloat16* __restrict__ A, const __nv_bfloat16* __restrict__ B,
         float* __restrict__ C, int N,
         long long sA, long long sB, long long sC)
{
    extern __shared__ char smem[];
    const u32 smem_base = smem_u32(smem);

    const int tid = threadIdx.x;
    const int wid = tid >> 5;
    const int lid = tid & 31;
    const int wm  = wid & 3;        // 4 warps along M (32 rows each)
    const int wn  = wid >> 2;       // 2 warps along N (64 cols each)

    A += (long long)blockIdx.z * sA;
    B += (long long)blockIdx.z * sB;
    C += (long long)blockIdx.z * sC;
    const int m0 = blockIdx.y * 128;
    const int n0 = blockIdx.x * 128;

    constexpr int NK = KTOT / 32;

    // cp.async chunk coords (2 chunks of 16B per thread per tile)
    const int r0c = tid >> 2,           q0 = tid & 3;
    const int r1c = (tid + 256) >> 2,   q1 = tid & 3;   // rows 64..127

    // ldmatrix source coords (within a stage)
    // A fragment: row = wm*32 + mt*16 + lid%16, kbyte = (lid/16)*16 (+ kstep*32)
    const int a_row = wm * 32 + (lid & 15);
    const int a_kb  = (lid >> 4) << 4;
    // B fragment (two n8 tiles per ldmatrix.x4):
    // n = wn*64 + bt*16 + ((lid/16)*8 + lid%8), kbyte = ((lid/8)&1)*16
    const int b_row = wn * 64 + ((lid >> 4) << 3) + (lid & 7);
    const int b_kb  = ((lid >> 3) & 1) << 4;

    float acc[2][8][4];
#pragma unroll
    for (int mt = 0; mt < 2; mt++)
#pragma unroll
        for (int nt = 0; nt < 8; nt++)
#pragma unroll
            for (int j = 0; j < 4; j++) acc[mt][nt][j] = 0.0f;

    // ---- async load of one stage ----
    auto load_stage = [&](int s, int kt) {
        const long long k0 = (long long)kt * 32;
        const u32 sa = smem_base + s * STAGE_B;
        const u32 sb = sa + TILE_B;
        CP_ASYNC_16(sa + r0c * 80 + q0 * 16, A + (long long)(m0 + r0c) * KTOT + k0 + q0 * 8);
        CP_ASYNC_16(sa + r1c * 80 + q1 * 16, A + (long long)(m0 + r1c) * KTOT + k0 + q1 * 8);
        CP_ASYNC_16(sb + r0c * 80 + q0 * 16, B + (long long)(n0 + r0c) * KTOT + k0 + q0 * 8);
        CP_ASYNC_16(sb + r1c * 80 + q1 * 16, B + (long long)(n0 + r1c) * KTOT + k0 + q1 * 8);
    };

    // prologue: fill STAGES-1 stages
#pragma unroll
    for (int s = 0; s < STAGES - 1; s++) {
        load_stage(s, s);
        CP_COMMIT();
    }

    for (int kt = 0; kt < NK; kt++) {
        CP_WAIT(STAGES - 2);
        __syncthreads();

        // issue loads for stage kt+STAGES-1 (slot freed by compute of kt-1)
        if (kt + STAGES - 1 < NK)
            load_stage((kt + STAGES - 1) % STAGES, kt + STAGES - 1);
        CP_COMMIT();

        const int s = kt % STAGES;
        const u32 sa = smem_base + s * STAGE_B;
        const u32 sb = sa + TILE_B;

#pragma unroll
        for (int kstep = 0; kstep < 2; kstep++) {
            u32 afr[2][4], bfr[8][2];
#pragma unroll
            for (int mt = 0; mt < 2; mt++)
                ldmatrix_x4(afr[mt][0], afr[mt][1], afr[mt][2], afr[mt][3],
                            sa + (a_row + mt * 16) * 80 + kstep * 32 + a_kb);
#pragma unroll
            for (int bt = 0; bt < 4; bt++) {
                u32 t0, t1, t2, t3;
                ldmatrix_x4(t0, t1, t2, t3,
                            sb + (b_row + bt * 16) * 80 + kstep * 32 + b_kb);
                bfr[bt * 2][0]     = t0; bfr[bt * 2][1]     = t1;
                bfr[bt * 2 + 1][0] = t2; bfr[bt * 2 + 1][1] = t3;
            }
#pragma unroll
            for (int mt = 0; mt < 2; mt++)
#pragma unroll
                for (int nt = 0; nt < 8; nt++)
                    mma_16816(acc[mt][nt], afr[mt], bfr[nt]);
        }
    }

    // ---- epilogue: direct f32 stores ----
#pragma unroll
    for (int mt = 0; mt < 2; mt++) {
        const int row = m0 + wm * 32 + mt * 16 + (lid >> 2);
#pragma unroll
        for (int nt = 0; nt < 8; nt++) {
            const int col = n0 + wn * 64 + nt * 8 + ((lid & 3) << 1);
            float2 v0 = make_float2(acc[mt][nt][0], acc[mt][nt][1]);
            float2 v1 = make_float2(acc[mt][nt][2], acc[mt][nt][3]);
            *(float2*)(C + (long long)row * N + col)       = v0;
            *(float2*)(C + (long long)(row + 8) * N + col) = v1;
        }
    }
}

// ---------------------------------------------------------------------------
// Split conversion: out[r][s*K + k], sections s=0,1,2.
//   A operands (Q, P): LO=1 -> (hi, lo, hi)
//   B operands (E)   : LO=2 -> (hi, hi, lo)
// Dot over concatenated K gives hi*hi + lo*hi + hi*lo  (= fp32 product - lo*lo)
// ---------------------------------------------------------------------------
template <int LO, int K>
__global__ void __launch_bounds__(256)
split3_kernel(const float* __restrict__ in, __nv_bfloat16* __restrict__ out,
              long long total)
{
    const long long n4 = total >> 2;
    for (long long i = (long long)blockIdx.x * blockDim.x + threadIdx.x;
         i < n4; i += (long long)gridDim.x * blockDim.x) {
        const long long e = i << 2;
        const long long r = e / K;
        const int k = (int)(e - r * (long long)K);
        const float4 x = *(const float4*)(in + e);
        const float xs[4] = {x.x, x.y, x.z, x.w};
        __nv_bfloat16 h[4], l[4];
#pragma unroll
        for (int j = 0; j < 4; j++) {
            h[j] = __float2bfloat16(xs[j]);
            l[j] = __float2bfloat16(xs[j] - __bfloat162float(h[j]));
        }
        __nv_bfloat16* o = out + r * (3LL * K) + k;
        __nv_bfloat162 hh0, hh1, ll0, ll1;
        hh0.x = h[0]; hh0.y = h[1]; hh1.x = h[2]; hh1.y = h[3];
        ll0.x = l[0]; ll0.y = l[1]; ll1.x = l[2]; ll1.y = l[3];
        *(__nv_bfloat162*)(o + 0) = hh0;
        *(__nv_bfloat162*)(o + 2) = hh1;
        *(__nv_bfloat162*)(o + K + 0) = (LO == 1) ? ll0 : hh0;
        *(__nv_bfloat162*)(o + K + 2) = (LO == 1) ? ll1 : hh1;
        *(__nv_bfloat162*)(o + 2 * K + 0) = (LO == 2) ? ll0 : hh0;
        *(__nv_bfloat162*)(o + 2 * K + 2) = (LO == 2) ? ll1 : hh1;
    }
}

// ---------------------------------------------------------------------------
// Transposing split for GEMM2's B operand:
//   ET3[b][n][s*TK + k] = split(E[b][k][n]), pattern (hi, hi, lo)
// ---------------------------------------------------------------------------
__global__ void __launch_bounds__(256)
transp_split_kernel(const float* __restrict__ E, __nv_bfloat16* __restrict__ ET)
{
    __shared__ float sm[32][33];
    const int b  = blockIdx.z;
    const int k0 = blockIdx.x * 32;
    const int n0 = blockIdx.y * 32;
    const float* Eb = E + (long long)b * TK * DIM;
    __nv_bfloat16* Tb = ET + (long long)b * DIM * K2;
    const int tx = threadIdx.x, ty = threadIdx.y;   // (32, 8)

#pragma unroll
    for (int i = 0; i < 32; i += 8)
        sm[ty + i][tx] = Eb[(long long)(k0 + ty + i) * DIM + n0 + tx];
    __syncthreads();

#pragma unroll
    for (int i = 0; i < 32; i += 8) {
        const int n = n0 + ty + i;
        const int k = k0 + tx;
        const float x = sm[tx][ty + i];
        const __nv_bfloat16 hi = __float2bfloat16(x);
        const __nv_bfloat16 lo = __float2bfloat16(x - __bfloat162float(hi));
        __nv_bfloat16* row = Tb + (long long)n * K2;
        row[k]          = hi;
        row[TK + k]     = hi;
        row[2 * TK + k] = lo;
    }
}

// ---------------------------------------------------------------------------
// Softmax over rows of 2048, fused with the P split (pattern hi, lo, hi).
// ---------------------------------------------------------------------------
__device__ __forceinline__ void write_split4(__nv_bfloat16* q, int k,
                                             float a, float b, float c, float d)
{
    const float xs[4] = {a, b, c, d};
    __nv_bfloat16 h[4], l[4];
#pragma unroll
    for (int j = 0; j < 4; j++) {
        h[j] = __float2bfloat16(xs[j]);
        l[j] = __float2bfloat16(xs[j] - __bfloat162float(h[j]));
    }
    __nv_bfloat162 hh0, hh1, ll0, ll1;
    hh0.x = h[0]; hh0.y = h[1]; hh1.x = h[2]; hh1.y = h[3];
    ll0.x = l[0]; ll0.y = l[1]; ll1.x = l[2]; ll1.y = l[3];
    *(__nv_bfloat162*)(q + k)              = hh0;
    *(__nv_bfloat162*)(q + k + 2)          = hh1;
    *(__nv_bfloat162*)(q + TK + k)         = ll0;
    *(__nv_bfloat162*)(q + TK + k + 2)     = ll1;
    *(__nv_bfloat162*)(q + 2 * TK + k)     = hh0;
    *(__nv_bfloat162*)(q + 2 * TK + k + 2) = hh1;
}

__global__ void __launch_bounds__(256, 4)
softmax_p3_kernel(const float* __restrict__ S, __nv_bfloat16* __restrict__ P3)
{
    __shared__ float red[8];
    __shared__ float red2[8];

    const long long row = blockIdx.x;
    const float* p = S + row * (long long)TK;
    __nv_bfloat16* q = P3 + row * (long long)K2;
    const int tid = threadIdx.x;

    const float4 v0 = *(const float4*)(p + tid * 4);
    const float4 v1 = *(const float4*)(p + 1024 + tid * 4);

    float m = fmaxf(fmaxf(fmaxf(v0.x, v0.y), fmaxf(v0.z, v0.w)),
                    fmaxf(fmaxf(v1.x, v1.y), fmaxf(v1.z, v1.w)));
#pragma unroll
    for (int o = 16; o > 0; o >>= 1)
        m = fmaxf(m, __shfl_xor_sync(0xffffffffu, m, o));
    if ((tid & 31) == 0) red[tid >> 5] = m;
    __syncthreads();
    m = fmaxf(fmaxf(fmaxf(red[0], red[1]), fmaxf(red[2], red[3])),
              fmaxf(fmaxf(red[4], red[5]), fmaxf(red[6], red[7])));

    float e[8];
    e[0] = __expf(v0.x - m); e[1] = __expf(v0.y - m);
    e[2] = __expf(v0.z - m); e[3] = __expf(v0.w - m);
    e[4] = __expf(v1.x - m); e[5] = __expf(v1.y - m);
    e[6] = __expf(v1.z - m); e[7] = __expf(v1.w - m);

    float s = ((e[0] + e[1]) + (e[2] + e[3])) + ((e[4] + e[5]) + (e[6] + e[7]));
#pragma unroll
    for (int o = 16; o > 0; o >>= 1)
        s += __shfl_xor_sync(0xffffffffu, s, o);
    if ((tid & 31) == 0) red2[tid >> 5] = s;
    __syncthreads();
    s = ((red2[0] + red2[1]) + (red2[2] + red2[3])) +
        ((red2[4] + red2[5]) + (red2[6] + red2[7]));

    const float inv = 1.0f / s;
    write_split4(q, tid * 4,        e[0] * inv, e[1] * inv, e[2] * inv, e[3] * inv);
    write_split4(q, 1024 + tid * 4, e[4] * inv, e[5] * inv, e[6] * inv, e[7] * inv);
}

// ---------------------------------------------------------------------------
// Entry point
// ---------------------------------------------------------------------------
extern "C" void kernel_launch(void* const* d_in, const int* in_sizes, int n_in,
                              void* d_out, int out_size)
{
    const float* Q = (const float*)d_in[0];  // [32, 512, 512]
    const float* E = (const float*)d_in[1];  // [32, 2048, 512]
    float* O = (float*)d_out;                // [32, 512, 512]

    __nv_bfloat16 *Q3, *E3, *P3, *ET3;
    float* S;
    cudaGetSymbolAddress((void**)&Q3,  g_Q3);
    cudaGetSymbolAddress((void**)&E3,  g_E3);
    cudaGetSymbolAddress((void**)&S,   g_S);
    cudaGetSymbolAddress((void**)&P3,  g_P3);
    cudaGetSymbolAddress((void**)&ET3, g_ET3);

    cudaFuncSetAttribute(gemm_mma<K1>, cudaFuncAttributeMaxDynamicSharedMemorySize, GEMM_SMEM);
    cudaFuncSetAttribute(gemm_mma<K2>, cudaFuncAttributeMaxDynamicSharedMemorySize, GEMM_SMEM);

    // operand conversions
    split3_kernel<1, DIM><<<8192, 256>>>(Q, Q3, (long long)BATCH * TQ * DIM);
    split3_kernel<2, DIM><<<32768, 256>>>(E, E3, (long long)BATCH * TK * DIM);
    transp_split_kernel<<<dim3(TK / 32, DIM / 32, BATCH), dim3(32, 8)>>>(E, ET3);

    // S = Q @ E^T   (M=512, N=2048, K'=1536)
    gemm_mma<K1><<<dim3(TK / 128, TQ / 128, BATCH), 256, GEMM_SMEM>>>(
        Q3, E3, S, TK,
        (long long)TQ * K1, (long long)TK * K1, (long long)TQ * TK);

    // softmax + P split
    softmax_p3_kernel<<<BATCH * TQ, 256>>>(S, P3);

    // O = P @ E     (M=512, N=512, K'=6144)
    gemm_mma<K2><<<dim3(DIM / 128, TQ / 128, BATCH), 256, GEMM_SMEM>>>(
        P3, ET3, O, DIM,
        (long long)TQ * K2, (long long)DIM * K2, (long long)TQ * DIM);
}

// round 11
// speedup vs baseline: 2.1941x; 1.1453x over previous
#include <cuda_runtime.h>
#include <cuda_bf16.h>

typedef unsigned int       u32;
typedef unsigned long long u64;

#define BATCH 32
#define TQ    512
#define TK    2048
#define DIM   512

// ---------------------------------------------------------------------------
// Scratch (device globals). 2-section split storage: row = [hi(K) | lo(K)].
// GEMM runs 3 passes: hi*hi + lo*hi + hi*lo  (= fp32 product minus O(2^-18) lo*lo)
// ---------------------------------------------------------------------------
__device__ __nv_bfloat16 g_Q2 [(size_t)BATCH * TQ  * 2 * DIM];  //  34 MB
__device__ __nv_bfloat16 g_E2 [(size_t)BATCH * TK  * 2 * DIM];  // 134 MB
__device__ float         g_S  [(size_t)BATCH * TQ  * TK];       // 134 MB
__device__ __nv_bfloat16 g_P2 [(size_t)BATCH * TQ  * 2 * TK];   // 134 MB
__device__ __nv_bfloat16 g_ET2[(size_t)BATCH * DIM * 2 * TK];   // 134 MB

// ---------------------------------------------------------------------------
// Baseline-PTX tensor-core helpers (sm_103 generic target: no tcgen05)
// ---------------------------------------------------------------------------
__device__ __forceinline__ u32 smem_u32(const void* p) {
    u32 a;
    asm("{ .reg .u64 t; cvta.to.shared.u64 t, %1; cvt.u32.u64 %0, t; }"
        : "=r"(a) : "l"(p));
    return a;
}

__device__ __forceinline__ void ldmatrix_x4(u32& r0, u32& r1, u32& r2, u32& r3,
                                            u32 addr) {
    asm volatile("ldmatrix.sync.aligned.m8n8.x4.shared.b16 {%0,%1,%2,%3}, [%4];"
                 : "=r"(r0), "=r"(r1), "=r"(r2), "=r"(r3) : "r"(addr));
}

__device__ __forceinline__ void mma_16816(float* c, const u32* a, const u32* b) {
    asm volatile(
        "mma.sync.aligned.m16n8k16.row.col.f32.bf16.bf16.f32 "
        "{%0,%1,%2,%3}, {%4,%5,%6,%7}, {%8,%9}, {%0,%1,%2,%3};"
        : "+f"(c[0]), "+f"(c[1]), "+f"(c[2]), "+f"(c[3])
        : "r"(a[0]), "r"(a[1]), "r"(a[2]), "r"(a[3]), "r"(b[0]), "r"(b[1]));
}

#define CP_ASYNC_16(saddr, gptr) \
    asm volatile("cp.async.cg.shared.global [%0], [%1], 16;" \
                 :: "r"(saddr), "l"(gptr) : "memory")
#define CP_COMMIT() asm volatile("cp.async.commit_group;" ::: "memory")
#define CP_WAIT(n)  asm volatile("cp.async.wait_group %0;" :: "n"(n) : "memory")

// ---------------------------------------------------------------------------
// Tiled NT GEMM (3-pass split): C[m][n] = sum_p sum_k A[m][aoff_p+k]*B[n][boff_p+k]
//   A: [M, 2K] bf16 (hi|lo), B: [N, 2K] bf16 (hi|lo), C f32.
// CTA 128x128, BK=64, 3-stage cp.async pipeline, 8 warps (32x64 warp tiles),
// software-pipelined ldmatrix fragments. Rows padded to 144B (conflict-free).
// ---------------------------------------------------------------------------
#define STAGES     3
#define ROWB       144                       // 64 bf16 data + 16B pad
#define TILE_BYTES (128 * ROWB)              // 18432
#define STAGE_BYTES (2 * TILE_BYTES)         // 36864
#define GEMM_SMEM  (STAGES * STAGE_BYTES)    // 110592

template <int K>
__global__ void __launch_bounds__(256, 2)
gemm_mma(const __nv_bfloat16* __restrict__ A, const __nv_bfloat16* __restrict__ B,
         float* __restrict__ C, int N,
         long long sA, long long sB, long long sC)
{
    extern __shared__ char smem[];
    const u32 smem_base = smem_u32(smem);

    constexpr int KT  = 2 * K;       // row stride in elements
    constexpr int NCH = K / 64;      // chunks per pass (power of 2)
    constexpr int NC  = 3 * NCH;

    const int tid = threadIdx.x;
    const int wid = tid >> 5;
    const int lid = tid & 31;
    const int wm  = wid & 3;         // 4 warps along M (32 rows each)
    const int wn  = wid >> 2;        // 2 warps along N (64 cols each)

    A += (long long)blockIdx.z * sA;
    B += (long long)blockIdx.z * sB;
    C += (long long)blockIdx.z * sC;
    const int m0 = blockIdx.y * 128;
    const int n0 = blockIdx.x * 128;

    // cp.async coords: 16B chunks; q constant per thread, 4 rows per tile
    const int q  = tid & 7;          // chunk within row (8 x 16B = 128B data)
    const int r0 = tid >> 3;         // base row (0..31), rows r0 + {0,32,64,96}

    // ldmatrix in-tile byte offsets
    const int a_off = (wm * 32 + (lid & 15)) * ROWB + ((lid >> 4) << 4);
    const int b_off = (wn * 64 + ((lid >> 4) << 3) + (lid & 7)) * ROWB +
                      (((lid >> 3) & 1) << 4);

    float acc[2][8][4];
#pragma unroll
    for (int mt = 0; mt < 2; mt++)
#pragma unroll
        for (int nt = 0; nt < 8; nt++)
#pragma unroll
            for (int j = 0; j < 4; j++) acc[mt][nt][j] = 0.0f;

    auto load_stage = [&](int s, int c) {
        const int pass = c / NCH;
        const int kk   = c - pass * NCH;
        const int ka   = ((pass == 1) ? K : 0) + kk * 64;
        const int kb   = ((pass == 2) ? K : 0) + kk * 64;
        const u32 sa = smem_base + s * STAGE_BYTES;
        const u32 sb = sa + TILE_BYTES;
        const __nv_bfloat16* Ap = A + (long long)(m0 + r0) * KT + ka + q * 8;
        const __nv_bfloat16* Bp = B + (long long)(n0 + r0) * KT + kb + q * 8;
#pragma unroll
        for (int i = 0; i < 4; i++) {
            CP_ASYNC_16(sa + (r0 + i * 32) * ROWB + q * 16, Ap + (long long)(i * 32) * KT);
            CP_ASYNC_16(sb + (r0 + i * 32) * ROWB + q * 16, Bp + (long long)(i * 32) * KT);
        }
    };

    // prologue: stages 0,1
    load_stage(0, 0); CP_COMMIT();
    if (NC > 1) load_stage(1, 1);
    CP_COMMIT();

    int sc = 0, sl = 2;
    for (int c = 0; c < NC; c++) {
        CP_WAIT(1);
        __syncthreads();

        if (c + 2 < NC) load_stage(sl, c + 2);
        CP_COMMIT();

        const u32 sa = smem_base + sc * STAGE_BYTES;
        const u32 sb = sa + TILE_BYTES;

        u32 ab[2][2][4];    // A frags, double-buffered per kstep
        u32 bb[2][2][2];    // B frags, double-buffered per bt pair

        // preload kstep 0
        ldmatrix_x4(ab[0][0][0], ab[0][0][1], ab[0][0][2], ab[0][0][3], sa + a_off);
        ldmatrix_x4(ab[0][1][0], ab[0][1][1], ab[0][1][2], ab[0][1][3],
                    sa + a_off + 16 * ROWB);
        ldmatrix_x4(bb[0][0][0], bb[0][0][1], bb[0][1][0], bb[0][1][1], sb + b_off);

#pragma unroll
        for (int ks = 0; ks < 4; ks++) {
            const int cb = ks & 1;
#pragma unroll
            for (int bt = 0; bt < 4; bt++) {
                if (bt < 3) {
                    const int nb = (bt + 1) & 1;
                    ldmatrix_x4(bb[nb][0][0], bb[nb][0][1], bb[nb][1][0], bb[nb][1][1],
                                sb + b_off + (bt + 1) * 16 * ROWB + ks * 32);
                } else if (ks < 3) {
                    const int na = (ks + 1) & 1;
                    ldmatrix_x4(ab[na][0][0], ab[na][0][1], ab[na][0][2], ab[na][0][3],
                                sa + a_off + (ks + 1) * 32);
                    ldmatrix_x4(ab[na][1][0], ab[na][1][1], ab[na][1][2], ab[na][1][3],
                                sa + a_off + 16 * ROWB + (ks + 1) * 32);
                    ldmatrix_x4(bb[0][0][0], bb[0][0][1], bb[0][1][0], bb[0][1][1],
                                sb + b_off + (ks + 1) * 32);
                }
                const int vb = bt & 1;
                mma_16816(acc[0][2 * bt],     ab[cb][0], bb[vb][0]);
                mma_16816(acc[0][2 * bt + 1], ab[cb][0], bb[vb][1]);
                mma_16816(acc[1][2 * bt],     ab[cb][1], bb[vb][0]);
                mma_16816(acc[1][2 * bt + 1], ab[cb][1], bb[vb][1]);
            }
        }

        sc = (sc + 1 == STAGES) ? 0 : sc + 1;
        sl = (sl + 1 == STAGES) ? 0 : sl + 1;
    }

    // ---- epilogue: direct f32 stores ----
#pragma unroll
    for (int mt = 0; mt < 2; mt++) {
        const int row = m0 + wm * 32 + mt * 16 + (lid >> 2);
#pragma unroll
        for (int nt = 0; nt < 8; nt++) {
            const int col = n0 + wn * 64 + nt * 8 + ((lid & 3) << 1);
            float2 v0 = make_float2(acc[mt][nt][0], acc[mt][nt][1]);
            float2 v1 = make_float2(acc[mt][nt][2], acc[mt][nt][3]);
            *(float2*)(C + (long long)row * N + col)       = v0;
            *(float2*)(C + (long long)(row + 8) * N + col) = v1;
        }
    }
}

// ---------------------------------------------------------------------------
// Fused E split: read E once, emit
//   E2 [b][t][d | DIM+d]   = (hi, lo)   (k-major, GEMM1 B operand)
//   ET2[b][d][t | TK+t]    = (hi, lo)   (transposed, GEMM2 B operand)
// ---------------------------------------------------------------------------
__global__ void __launch_bounds__(256)
esplit_kernel(const float* __restrict__ E, __nv_bfloat16* __restrict__ E2,
              __nv_bfloat16* __restrict__ ET2)
{
    __shared__ float sm[32][33];
    const int b  = blockIdx.z;
    const int t0 = blockIdx.x * 32;   // token
    const int d0 = blockIdx.y * 32;   // dim
    const float* Eb = E + (long long)b * TK * DIM;
    __nv_bfloat16* E2b  = E2  + (long long)b * TK  * (2 * DIM);
    __nv_bfloat16* ET2b = ET2 + (long long)b * DIM * (2 * TK);
    const int tx = threadIdx.x, ty = threadIdx.y;   // (32, 8)

#pragma unroll
    for (int i = 0; i < 32; i += 8) {
        const float x = Eb[(long long)(t0 + ty + i) * DIM + d0 + tx];
        sm[ty + i][tx] = x;
        const __nv_bfloat16 hi = __float2bfloat16(x);
        const __nv_bfloat16 lo = __float2bfloat16(x - __bfloat162float(hi));
        __nv_bfloat16* row = E2b + (long long)(t0 + ty + i) * (2 * DIM);
        row[d0 + tx]       = hi;
        row[DIM + d0 + tx] = lo;
    }
    __syncthreads();

#pragma unroll
    for (int i = 0; i < 32; i += 8) {
        const int d = d0 + ty + i;
        const int t = t0 + tx;
        const float x = sm[tx][ty + i];
        const __nv_bfloat16 hi = __float2bfloat16(x);
        const __nv_bfloat16 lo = __float2bfloat16(x - __bfloat162float(hi));
        __nv_bfloat16* row = ET2b + (long long)d * (2 * TK);
        row[t]      = hi;
        row[TK + t] = lo;
    }
}

// ---------------------------------------------------------------------------
// Q split: out[r][k] = hi, out[r][K+k] = lo  (row length 2K)
// ---------------------------------------------------------------------------
template <int K>
__global__ void __launch_bounds__(256)
split2_kernel(const float* __restrict__ in, __nv_bfloat16* __restrict__ out,
              long long total)
{
    const long long n4 = total >> 2;
    for (long long i = (long long)blockIdx.x * blockDim.x + threadIdx.x;
         i < n4; i += (long long)gridDim.x * blockDim.x) {
        const long long e = i << 2;
        const long long r = e / K;
        const int k = (int)(e - r * (long long)K);
        const float4 x = *(const float4*)(in + e);
        const float xs[4] = {x.x, x.y, x.z, x.w};
        __nv_bfloat16 h[4], l[4];
#pragma unroll
        for (int j = 0; j < 4; j++) {
            h[j] = __float2bfloat16(xs[j]);
            l[j] = __float2bfloat16(xs[j] - __bfloat162float(h[j]));
        }
        __nv_bfloat16* o = out + r * (2LL * K) + k;
        __nv_bfloat162 hh0, hh1, ll0, ll1;
        hh0.x = h[0]; hh0.y = h[1]; hh1.x = h[2]; hh1.y = h[3];
        ll0.x = l[0]; ll0.y = l[1]; ll1.x = l[2]; ll1.y = l[3];
        *(__nv_bfloat162*)(o + 0)     = hh0;
        *(__nv_bfloat162*)(o + 2)     = hh1;
        *(__nv_bfloat162*)(o + K)     = ll0;
        *(__nv_bfloat162*)(o + K + 2) = ll1;
    }
}

// ---------------------------------------------------------------------------
// Softmax over rows of 2048, fused with the P split (hi | lo, row length 4096)
// ---------------------------------------------------------------------------
__device__ __forceinline__ void write_split4(__nv_bfloat16* q, int k,
                                             float a, float b, float c, float d)
{
    const float xs[4] = {a, b, c, d};
    __nv_bfloat16 h[4], l[4];
#pragma unroll
    for (int j = 0; j < 4; j++) {
        h[j] = __float2bfloat16(xs[j]);
        l[j] = __float2bfloat16(xs[j] - __bfloat162float(h[j]));
    }
    __nv_bfloat162 hh0, hh1, ll0, ll1;
    hh0.x = h[0]; hh0.y = h[1]; hh1.x = h[2]; hh1.y = h[3];
    ll0.x = l[0]; ll0.y = l[1]; ll1.x = l[2]; ll1.y = l[3];
    *(__nv_bfloat162*)(q + k)          = hh0;
    *(__nv_bfloat162*)(q + k + 2)      = hh1;
    *(__nv_bfloat162*)(q + TK + k)     = ll0;
    *(__nv_bfloat162*)(q + TK + k + 2) = ll1;
}

__global__ void __launch_bounds__(256, 4)
softmax_p2_kernel(const float* __restrict__ S, __nv_bfloat16* __restrict__ P2)
{
    __shared__ float red[8];
    __shared__ float red2[8];

    const long long row = blockIdx.x;
    const float* p = S + row * (long long)TK;
    __nv_bfloat16* q = P2 + row * (long long)(2 * TK);
    const int tid = threadIdx.x;

    const float4 v0 = *(const float4*)(p + tid * 4);
    const float4 v1 = *(const float4*)(p + 1024 + tid * 4);

    float m = fmaxf(fmaxf(fmaxf(v0.x, v0.y), fmaxf(v0.z, v0.w)),
                    fmaxf(fmaxf(v1.x, v1.y), fmaxf(v1.z, v1.w)));
#pragma unroll
    for (int o = 16; o > 0; o >>= 1)
        m = fmaxf(m, __shfl_xor_sync(0xffffffffu, m, o));
    if ((tid & 31) == 0) red[tid >> 5] = m;
    __syncthreads();
    m = fmaxf(fmaxf(fmaxf(red[0], red[1]), fmaxf(red[2], red[3])),
              fmaxf(fmaxf(red[4], red[5]), fmaxf(red[6], red[7])));

    float e[8];
    e[0] = __expf(v0.x - m); e[1] = __expf(v0.y - m);
    e[2] = __expf(v0.z - m); e[3] = __expf(v0.w - m);
    e[4] = __expf(v1.x - m); e[5] = __expf(v1.y - m);
    e[6] = __expf(v1.z - m); e[7] = __expf(v1.w - m);

    float s = ((e[0] + e[1]) + (e[2] + e[3])) + ((e[4] + e[5]) + (e[6] + e[7]));
#pragma unroll
    for (int o = 16; o > 0; o >>= 1)
        s += __shfl_xor_sync(0xffffffffu, s, o);
    if ((tid & 31) == 0) red2[tid >> 5] = s;
    __syncthreads();
    s = ((red2[0] + red2[1]) + (red2[2] + red2[3])) +
        ((red2[4] + red2[5]) + (red2[6] + red2[7]));

    const float inv = 1.0f / s;
    write_split4(q, tid * 4,        e[0] * inv, e[1] * inv, e[2] * inv, e[3] * inv);
    write_split4(q, 1024 + tid * 4, e[4] * inv, e[5] * inv, e[6] * inv, e[7] * inv);
}

// ---------------------------------------------------------------------------
// Entry point
// ---------------------------------------------------------------------------
extern "C" void kernel_launch(void* const* d_in, const int* in_sizes, int n_in,
                              void* d_out, int out_size)
{
    const float* Q = (const float*)d_in[0];  // [32, 512, 512]
    const float* E = (const float*)d_in[1];  // [32, 2048, 512]
    float* O = (float*)d_out;                // [32, 512, 512]

    __nv_bfloat16 *Q2, *E2, *P2, *ET2;
    float* S;
    cudaGetSymbolAddress((void**)&Q2,  g_Q2);
    cudaGetSymbolAddress((void**)&E2,  g_E2);
    cudaGetSymbolAddress((void**)&S,   g_S);
    cudaGetSymbolAddress((void**)&P2,  g_P2);
    cudaGetSymbolAddress((void**)&ET2, g_ET2);

    cudaFuncSetAttribute(gemm_mma<DIM>, cudaFuncAttributeMaxDynamicSharedMemorySize, GEMM_SMEM);
    cudaFuncSetAttribute(gemm_mma<TK>,  cudaFuncAttributeMaxDynamicSharedMemorySize, GEMM_SMEM);

    // operand conversions
    split2_kernel<DIM><<<8192, 256>>>(Q, Q2, (long long)BATCH * TQ * DIM);
    esplit_kernel<<<dim3(TK / 32, DIM / 32, BATCH), dim3(32, 8)>>>(E, E2, ET2);

    // S = Q @ E^T   (M=512, N=2048, per-section K=512, 3 passes)
    gemm_mma<DIM><<<dim3(TK / 128, TQ / 128, BATCH), 256, GEMM_SMEM>>>(
        Q2, E2, S, TK,
        (long long)TQ * 2 * DIM, (long long)TK * 2 * DIM, (long long)TQ * TK);

    // softmax + P split
    softmax_p2_kernel<<<BATCH * TQ, 256>>>(S, P2);

    // O = P @ E     (M=512, N=512, per-section K=2048, 3 passes)
    gemm_mma<TK><<<dim3(DIM / 128, TQ / 128, BATCH), 256, GEMM_SMEM>>>(
        P2, ET2, O, DIM,
        (long long)TQ * 2 * TK, (long long)DIM * 2 * TK, (long long)TQ * DIM);
}

// round 12
// speedup vs baseline: 2.2150x; 1.0095x over previous
#include <cuda_runtime.h>
#include <cuda_bf16.h>

typedef unsigned int       u32;
typedef unsigned long long u64;

#define BATCH 32
#define TQ    512
#define TK    2048
#define DIM   512

// ---------------------------------------------------------------------------
// Scratch (device globals). 2-section split storage: row = [hi(K) | lo(K)].
// Product uses 3 partial passes: hi*hi + lo*hi + hi*lo (fp32 minus O(2^-18))
// ---------------------------------------------------------------------------
__device__ __nv_bfloat16 g_Q2 [(size_t)BATCH * TQ  * 2 * DIM];  //  34 MB
__device__ __nv_bfloat16 g_E2 [(size_t)BATCH * TK  * 2 * DIM];  // 134 MB
__device__ float         g_S  [(size_t)BATCH * TQ  * TK];       // 134 MB
__device__ __nv_bfloat16 g_ET2[(size_t)BATCH * DIM * 2 * TK];   // 134 MB
__device__ float2        g_stat[(size_t)BATCH * TQ * (TK / 128)]; // 2 MB
__device__ float2        g_row [(size_t)BATCH * TQ];              // 128 KB

// ---------------------------------------------------------------------------
// Baseline-PTX tensor-core helpers (sm_103 generic target: no tcgen05)
// ---------------------------------------------------------------------------
__device__ __forceinline__ u32 smem_u32(const void* p) {
    u32 a;
    asm("{ .reg .u64 t; cvta.to.shared.u64 t, %1; cvt.u32.u64 %0, t; }"
        : "=r"(a) : "l"(p));
    return a;
}

__device__ __forceinline__ void ldmatrix_x4(u32& r0, u32& r1, u32& r2, u32& r3,
                                            u32 addr) {
    asm volatile("ldmatrix.sync.aligned.m8n8.x4.shared.b16 {%0,%1,%2,%3}, [%4];"
                 : "=r"(r0), "=r"(r1), "=r"(r2), "=r"(r3) : "r"(addr));
}

__device__ __forceinline__ void mma_16816(float* c, const u32* a, const u32* b) {
    asm volatile(
        "mma.sync.aligned.m16n8k16.row.col.f32.bf16.bf16.f32 "
        "{%0,%1,%2,%3}, {%4,%5,%6,%7}, {%8,%9}, {%0,%1,%2,%3};"
        : "+f"(c[0]), "+f"(c[1]), "+f"(c[2]), "+f"(c[3])
        : "r"(a[0]), "r"(a[1]), "r"(a[2]), "r"(a[3]), "r"(b[0]), "r"(b[1]));
}

#define CP_ASYNC_16(saddr, gptr) \
    asm volatile("cp.async.cg.shared.global [%0], [%1], 16;" \
                 :: "r"(saddr), "l"(gptr) : "memory")
#define CP_COMMIT() asm volatile("cp.async.commit_group;" ::: "memory")
#define CP_WAIT(n)  asm volatile("cp.async.wait_group %0;" :: "n"(n) : "memory")

// ===========================================================================
// GEMM1: S = Q @ E^T (3-pass split, K=512/section) + per-tile softmax stats.
// CTA 128x128, BK=64, 3-stage cp.async, 8 warps (32m x 64n warp tiles).
// Identical mainloop to the proven R11 kernel; adds a stats epilogue that
// writes (rowmax, sum exp(s - rowmax)) per (row, 128-col tile) to g_stat.
// ===========================================================================
#define STAGES     3
#define ROWB       144
#define TILE_BYTES (128 * ROWB)
#define STAGE_BYTES (2 * TILE_BYTES)
#define GEMM_SMEM  (STAGES * STAGE_BYTES)    // 110592

__global__ void __launch_bounds__(256, 2)
gemm1_stats(const __nv_bfloat16* __restrict__ A, const __nv_bfloat16* __restrict__ B,
            float* __restrict__ C, float2* __restrict__ stat)
{
    extern __shared__ char smem[];
    const u32 smem_base = smem_u32(smem);

    constexpr int K   = DIM;
    constexpr int KT  = 2 * K;
    constexpr int NCH = K / 64;
    constexpr int NC  = 3 * NCH;
    constexpr int N   = TK;

    const int tid = threadIdx.x;
    const int wid = tid >> 5;
    const int lid = tid & 31;
    const int wm  = wid & 3;
    const int wn  = wid >> 2;

    A += (long long)blockIdx.z * (TQ * (long long)KT);
    B += (long long)blockIdx.z * (TK * (long long)KT);
    C += (long long)blockIdx.z * ((long long)TQ * TK);
    const int m0 = blockIdx.y * 128;
    const int n0 = blockIdx.x * 128;

    const int q  = tid & 7;
    const int r0 = tid >> 3;

    const int a_off = (wm * 32 + (lid & 15)) * ROWB + ((lid >> 4) << 4);
    const int b_off = (wn * 64 + ((lid >> 4) << 3) + (lid & 7)) * ROWB +
                      (((lid >> 3) & 1) << 4);

    float acc[2][8][4];
#pragma unroll
    for (int mt = 0; mt < 2; mt++)
#pragma unroll
        for (int nt = 0; nt < 8; nt++)
#pragma unroll
            for (int j = 0; j < 4; j++) acc[mt][nt][j] = 0.0f;

    auto load_stage = [&](int s, int c) {
        const int pass = c / NCH;
        const int kk   = c - pass * NCH;
        const int ka   = ((pass == 1) ? K : 0) + kk * 64;
        const int kb   = ((pass == 2) ? K : 0) + kk * 64;
        const u32 sa = smem_base + s * STAGE_BYTES;
        const u32 sb = sa + TILE_BYTES;
        const __nv_bfloat16* Ap = A + (long long)(m0 + r0) * KT + ka + q * 8;
        const __nv_bfloat16* Bp = B + (long long)(n0 + r0) * KT + kb + q * 8;
#pragma unroll
        for (int i = 0; i < 4; i++) {
            CP_ASYNC_16(sa + (r0 + i * 32) * ROWB + q * 16, Ap + (long long)(i * 32) * KT);
            CP_ASYNC_16(sb + (r0 + i * 32) * ROWB + q * 16, Bp + (long long)(i * 32) * KT);
        }
    };

    load_stage(0, 0); CP_COMMIT();
    load_stage(1, 1); CP_COMMIT();

    int sc = 0, sl = 2;
    for (int c = 0; c < NC; c++) {
        CP_WAIT(1);
        __syncthreads();

        if (c + 2 < NC) load_stage(sl, c + 2);
        CP_COMMIT();

        const u32 sa = smem_base + sc * STAGE_BYTES;
        const u32 sb = sa + TILE_BYTES;

        u32 ab[2][2][4];
        u32 bb[2][2][2];

        ldmatrix_x4(ab[0][0][0], ab[0][0][1], ab[0][0][2], ab[0][0][3], sa + a_off);
        ldmatrix_x4(ab[0][1][0], ab[0][1][1], ab[0][1][2], ab[0][1][3],
                    sa + a_off + 16 * ROWB);
        ldmatrix_x4(bb[0][0][0], bb[0][0][1], bb[0][1][0], bb[0][1][1], sb + b_off);

#pragma unroll
        for (int ks = 0; ks < 4; ks++) {
            const int cb = ks & 1;
#pragma unroll
            for (int bt = 0; bt < 4; bt++) {
                if (bt < 3) {
                    const int nb = (bt + 1) & 1;
                    ldmatrix_x4(bb[nb][0][0], bb[nb][0][1], bb[nb][1][0], bb[nb][1][1],
                                sb + b_off + (bt + 1) * 16 * ROWB + ks * 32);
                } else if (ks < 3) {
                    const int na = (ks + 1) & 1;
                    ldmatrix_x4(ab[na][0][0], ab[na][0][1], ab[na][0][2], ab[na][0][3],
                                sa + a_off + (ks + 1) * 32);
                    ldmatrix_x4(ab[na][1][0], ab[na][1][1], ab[na][1][2], ab[na][1][3],
                                sa + a_off + 16 * ROWB + (ks + 1) * 32);
                    ldmatrix_x4(bb[0][0][0], bb[0][0][1], bb[0][1][0], bb[0][1][1],
                                sb + b_off + (ks + 1) * 32);
                }
                const int vb = bt & 1;
                mma_16816(acc[0][2 * bt],     ab[cb][0], bb[vb][0]);
                mma_16816(acc[0][2 * bt + 1], ab[cb][0], bb[vb][1]);
                mma_16816(acc[1][2 * bt],     ab[cb][1], bb[vb][0]);
                mma_16816(acc[1][2 * bt + 1], ab[cb][1], bb[vb][1]);
            }
        }

        sc = (sc + 1 == STAGES) ? 0 : sc + 1;
        sl = (sl + 1 == STAGES) ? 0 : sl + 1;
    }

    // ---- store S ----
#pragma unroll
    for (int mt = 0; mt < 2; mt++) {
        const int row = m0 + wm * 32 + mt * 16 + (lid >> 2);
#pragma unroll
        for (int nt = 0; nt < 8; nt++) {
            const int col = n0 + wn * 64 + nt * 8 + ((lid & 3) << 1);
            *(float2*)(C + (long long)row * N + col) =
                make_float2(acc[mt][nt][0], acc[mt][nt][1]);
            *(float2*)(C + (long long)(row + 8) * N + col) =
                make_float2(acc[mt][nt][2], acc[mt][nt][3]);
        }
    }

    // ---- softmax tile stats (rowmax, sum exp) ----
    CP_WAIT(0);
    __syncthreads();                       // stage smem now reusable
    float* smax = (float*)smem;            // [2][128]
    float* ssum = (float*)(smem + 1024);   // [2][128]

    float mrow[2][2];
#pragma unroll
    for (int mt = 0; mt < 2; mt++)
#pragma unroll
        for (int h = 0; h < 2; h++) {
            float m = -3.0e38f;
#pragma unroll
            for (int nt = 0; nt < 8; nt++)
                m = fmaxf(m, fmaxf(acc[mt][nt][2 * h], acc[mt][nt][2 * h + 1]));
            m = fmaxf(m, __shfl_xor_sync(0xffffffffu, m, 1));
            m = fmaxf(m, __shfl_xor_sync(0xffffffffu, m, 2));
            const int rloc = wm * 32 + mt * 16 + h * 8 + (lid >> 2);
            if ((lid & 3) == 0) smax[wn * 128 + rloc] = m;
        }
    __syncthreads();
#pragma unroll
    for (int mt = 0; mt < 2; mt++)
#pragma unroll
        for (int h = 0; h < 2; h++) {
            const int rloc = wm * 32 + mt * 16 + h * 8 + (lid >> 2);
            mrow[mt][h] = fmaxf(smax[rloc], smax[128 + rloc]);
            float s = 0.0f;
#pragma unroll
            for (int nt = 0; nt < 8; nt++)
                s += __expf(acc[mt][nt][2 * h] - mrow[mt][h]) +
                     __expf(acc[mt][nt][2 * h + 1] - mrow[mt][h]);
            s += __shfl_xor_sync(0xffffffffu, s, 1);
            s += __shfl_xor_sync(0xffffffffu, s, 2);
            if ((lid & 3) == 0) ssum[wn * 128 + rloc] = s;
        }
    __syncthreads();
    if (wn == 0 && (lid & 3) == 0) {
#pragma unroll
        for (int mt = 0; mt < 2; mt++)
#pragma unroll
            for (int h = 0; h < 2; h++) {
                const int rloc = wm * 32 + mt * 16 + h * 8 + (lid >> 2);
                const long long row = (long long)blockIdx.z * TQ + m0 + rloc;
                stat[row * 16 + blockIdx.x] =
                    make_float2(mrow[mt][h], ssum[rloc] + ssum[128 + rloc]);
            }
    }
}

// ---------------------------------------------------------------------------
// Reduce 16 tile stats per row -> (rowmax, 1/rowsum)
// ---------------------------------------------------------------------------
__global__ void __launch_bounds__(256)
rowstat_kernel(const float2* __restrict__ stat, float2* __restrict__ rowinfo)
{
    const int idx = blockIdx.x * 256 + threadIdx.x;   // 16384 rows
    const float2* t = stat + (long long)idx * 16;
    float m = t[0].x;
#pragma unroll
    for (int i = 1; i < 16; i++) m = fmaxf(m, t[i].x);
    float s = 0.0f;
#pragma unroll
    for (int i = 0; i < 16; i++) s += t[i].y * __expf(t[i].x - m);
    rowinfo[idx] = make_float2(m, 1.0f / s);
}

// ===========================================================================
// GEMM2 (fused softmax): O = softmax(S) @ V, V = E.
//   A: S fp32 [TQ, TK] -> P = expf(s-m)*inv, split hi/lo in-kernel.
//   B: ET2 [DIM, hi(TK)|lo(TK)] bf16 k-contiguous.
// CTA 64m x 128n, k-chunk 64, chunk-major 3 sub-passes
// (A_hi*B_hi, A_lo*B_hi, A_hi*B_lo), 2-stage pipeline, 8 warps (32x32 tiles).
// ===========================================================================
#define ROWB2  272                          // 128 bf16 (hi|lo) + 16B pad
#define A2_ST  (64 * ROWB2)                 // 17408
#define B2_ST  (128 * ROWB2)                // 34816
#define STG2   (A2_ST + B2_ST)              // 52224
#define GEMM2_SMEM (2 * STG2)               // 104448

__global__ void __launch_bounds__(256, 2)
gemm2_fused(const float* __restrict__ S, const __nv_bfloat16* __restrict__ Bm,
            const float2* __restrict__ rowinfo, float* __restrict__ O)
{
    extern __shared__ char smem[];
    const u32 smem_base = smem_u32(smem);

    constexpr int NC = TK / 64;   // 32 chunks

    const int tid = threadIdx.x;
    const int wid = tid >> 5;
    const int lid = tid & 31;
    const int wm  = wid & 1;      // 2 warps along M (32 rows)
    const int wn  = wid >> 1;     // 4 warps along N (32 cols)

    const int bz = blockIdx.z;
    const int m0 = blockIdx.y * 64;
    const int n0 = blockIdx.x * 128;

    // A loader: 4 threads per row, 16 fp32 each
    const int ar = tid >> 2;            // 0..63
    const int aq = tid & 3;             // 16-el group
    const float* Ap = S + ((long long)bz * TQ + m0 + ar) * TK + aq * 16;
    const float2 ri = rowinfo[(long long)bz * TQ + m0 + ar];
    const float m_r = ri.x, inv_r = ri.y;

    // B loader: bs = 16B granule within row (0..15: 8 hi + 8 lo), rows br0+16i
    const int bs  = tid & 15;
    const int br0 = tid >> 4;           // 0..15
    const int bko = ((bs >> 3) & 1) * TK + (bs & 7) * 8;
    const __nv_bfloat16* Bp = Bm + ((long long)bz * DIM + n0) * (2 * TK) + bko;

    // fragment addresses (within stage)
    const int a_base = (wm * 32 + (lid & 15)) * ROWB2 + ((lid >> 4) << 4);
    const int b_base = (wn * 32 + ((lid >> 4) << 3) + (lid & 7)) * ROWB2 +
                       (((lid >> 3) & 1) << 4);

    float acc[2][4][4];
#pragma unroll
    for (int mt = 0; mt < 2; mt++)
#pragma unroll
        for (int nt = 0; nt < 4; nt++)
#pragma unroll
            for (int j = 0; j < 4; j++) acc[mt][nt][j] = 0.0f;

    float4 av[4];

    auto lda = [&](int c) {
#pragma unroll
        for (int i = 0; i < 4; i++) av[i] = *(const float4*)(Ap + c * 64 + i * 4);
    };
    auto ldb = [&](int st, int c) {
        const u32 sb = smem_base + st * STG2 + A2_ST;
#pragma unroll
        for (int i = 0; i < 8; i++)
            CP_ASYNC_16(sb + (br0 + 16 * i) * ROWB2 + bs * 16,
                        Bp + (long long)(br0 + 16 * i) * (2 * TK) + c * 64);
    };
    auto cvta = [&](int st) {
        // P = expf(s - m) * inv ; split hi/lo ; store 16 els
        char* dst = smem + st * STG2 + ar * ROWB2 + aq * 32;
        u32 hi[8], lo[8];
        const float* f = (const float*)av;
#pragma unroll
        for (int j = 0; j < 8; j++) {
            const float p0 = __expf(f[2 * j]     - m_r) * inv_r;
            const float p1 = __expf(f[2 * j + 1] - m_r) * inv_r;
            const __nv_bfloat16 h0 = __float2bfloat16(p0);
            const __nv_bfloat16 h1 = __float2bfloat16(p1);
            const __nv_bfloat16 l0 = __float2bfloat16(p0 - __bfloat162float(h0));
            const __nv_bfloat16 l1 = __float2bfloat16(p1 - __bfloat162float(h1));
            __nv_bfloat162 hh, ll;
            hh.x = h0; hh.y = h1; ll.x = l0; ll.y = l1;
            hi[j] = *(u32*)&hh; lo[j] = *(u32*)&ll;
        }
        *(uint4*)(dst)            = make_uint4(hi[0], hi[1], hi[2], hi[3]);
        *(uint4*)(dst + 16)       = make_uint4(hi[4], hi[5], hi[6], hi[7]);
        *(uint4*)(dst + 128)      = make_uint4(lo[0], lo[1], lo[2], lo[3]);
        *(uint4*)(dst + 128 + 16) = make_uint4(lo[4], lo[5], lo[6], lo[7]);
    };

    // prologue: chunk 0 into stage 0
    lda(0);
    ldb(0, 0); CP_COMMIT();
    cvta(0);

    for (int c = 0; c < NC; c++) {
        CP_WAIT(0);
        __syncthreads();

        if (c + 1 < NC) {
            lda(c + 1);                       // LDG in flight during compute
            ldb((c + 1) & 1, c + 1);
            CP_COMMIT();
        }

        const u32 sa = smem_base + (c & 1) * STG2;
        const u32 sb = sa + A2_ST;

        u32 af[2][2][4], bf[2][2][4];
        // preload step 0 (sub0, ks0)
        ldmatrix_x4(af[0][0][0], af[0][0][1], af[0][0][2], af[0][0][3], sa + a_base);
        ldmatrix_x4(af[0][1][0], af[0][1][1], af[0][1][2], af[0][1][3],
                    sa + a_base + 16 * ROWB2);
        ldmatrix_x4(bf[0][0][0], bf[0][0][1], bf[0][0][2], bf[0][0][3], sb + b_base);
        ldmatrix_x4(bf[0][1][0], bf[0][1][1], bf[0][1][2], bf[0][1][3],
                    sb + b_base + 16 * ROWB2);

#pragma unroll
        for (int s = 0; s < 12; s++) {
            const int cb = s & 1;
            if (s < 11) {
                const int s1   = s + 1;
                const int sub  = s1 >> 2;
                const int ks   = s1 & 3;
                const int aoff = ((sub == 1) ? 128 : 0) + ks * 32;
                const int boff = ((sub == 2) ? 128 : 0) + ks * 32;
                const int nb = s1 & 1;
                ldmatrix_x4(af[nb][0][0], af[nb][0][1], af[nb][0][2], af[nb][0][3],
                            sa + a_base + aoff);
                ldmatrix_x4(af[nb][1][0], af[nb][1][1], af[nb][1][2], af[nb][1][3],
                            sa + a_base + aoff + 16 * ROWB2);
                ldmatrix_x4(bf[nb][0][0], bf[nb][0][1], bf[nb][0][2], bf[nb][0][3],
                            sb + b_base + boff);
                ldmatrix_x4(bf[nb][1][0], bf[nb][1][1], bf[nb][1][2], bf[nb][1][3],
                            sb + b_base + boff + 16 * ROWB2);
            }
#pragma unroll
            for (int mt = 0; mt < 2; mt++)
#pragma unroll
                for (int p = 0; p < 2; p++) {
                    mma_16816(acc[mt][2 * p],     af[cb][mt], &bf[cb][p][0]);
                    mma_16816(acc[mt][2 * p + 1], af[cb][mt], &bf[cb][p][2]);
                }
        }

        if (c + 1 < NC) cvta((c + 1) & 1);    // STS after MMAs (LDG latency hidden)
    }

    // ---- epilogue: O f32 ----
    O += (long long)bz * TQ * DIM;
#pragma unroll
    for (int mt = 0; mt < 2; mt++) {
        const int row = m0 + wm * 32 + mt * 16 + (lid >> 2);
#pragma unroll
        for (int nt = 0; nt < 4; nt++) {
            const int col = n0 + wn * 32 + nt * 8 + ((lid & 3) << 1);
            *(float2*)(O + (long long)row * DIM + col) =
                make_float2(acc[mt][nt][0], acc[mt][nt][1]);
            *(float2*)(O + (long long)(row + 8) * DIM + col) =
                make_float2(acc[mt][nt][2], acc[mt][nt][3]);
        }
    }
}

// ---------------------------------------------------------------------------
// Fused E split: read E once, emit E2 (k-major hi|lo) and ET2 (transposed)
// ---------------------------------------------------------------------------
__global__ void __launch_bounds__(256)
esplit_kernel(const float* __restrict__ E, __nv_bfloat16* __restrict__ E2,
              __nv_bfloat16* __restrict__ ET2)
{
    __shared__ float sm[32][33];
    const int b  = blockIdx.z;
    const int t0 = blockIdx.x * 32;
    const int d0 = blockIdx.y * 32;
    const float* Eb = E + (long long)b * TK * DIM;
    __nv_bfloat16* E2b  = E2  + (long long)b * TK  * (2 * DIM);
    __nv_bfloat16* ET2b = ET2 + (long long)b * DIM * (2 * TK);
    const int tx = threadIdx.x, ty = threadIdx.y;

#pragma unroll
    for (int i = 0; i < 32; i += 8) {
        const float x = Eb[(long long)(t0 + ty + i) * DIM + d0 + tx];
        sm[ty + i][tx] = x;
        const __nv_bfloat16 hi = __float2bfloat16(x);
        const __nv_bfloat16 lo = __float2bfloat16(x - __bfloat162float(hi));
        __nv_bfloat16* row = E2b + (long long)(t0 + ty + i) * (2 * DIM);
        row[d0 + tx]       = hi;
        row[DIM + d0 + tx] = lo;
    }
    __syncthreads();

#pragma unroll
    for (int i = 0; i < 32; i += 8) {
        const int d = d0 + ty + i;
        const int t = t0 + tx;
        const float x = sm[tx][ty + i];
        const __nv_bfloat16 hi = __float2bfloat16(x);
        const __nv_bfloat16 lo = __float2bfloat16(x - __bfloat162float(hi));
        __nv_bfloat16* row = ET2b + (long long)d * (2 * TK);
        row[t]      = hi;
        row[TK + t] = lo;
    }
}

// ---------------------------------------------------------------------------
// Q split: out[r][k] = hi, out[r][K+k] = lo
// ---------------------------------------------------------------------------
template <int K>
__global__ void __launch_bounds__(256)
split2_kernel(const float* __restrict__ in, __nv_bfloat16* __restrict__ out,
              long long total)
{
    const long long n4 = total >> 2;
    for (long long i = (long long)blockIdx.x * blockDim.x + threadIdx.x;
         i < n4; i += (long long)gridDim.x * blockDim.x) {
        const long long e = i << 2;
        const long long r = e / K;
        const int k = (int)(e - r * (long long)K);
        const float4 x = *(const float4*)(in + e);
        const float xs[4] = {x.x, x.y, x.z, x.w};
        __nv_bfloat16 h[4], l[4];
#pragma unroll
        for (int j = 0; j < 4; j++) {
            h[j] = __float2bfloat16(xs[j]);
            l[j] = __float2bfloat16(xs[j] - __bfloat162float(h[j]));
        }
        __nv_bfloat16* o = out + r * (2LL * K) + k;
        __nv_bfloat162 hh0, hh1, ll0, ll1;
        hh0.x = h[0]; hh0.y = h[1]; hh1.x = h[2]; hh1.y = h[3];
        ll0.x = l[0]; ll0.y = l[1]; ll1.x = l[2]; ll1.y = l[3];
        *(__nv_bfloat162*)(o + 0)     = hh0;
        *(__nv_bfloat162*)(o + 2)     = hh1;
        *(__nv_bfloat162*)(o + K)     = ll0;
        *(__nv_bfloat162*)(o + K + 2) = ll1;
    }
}

// ---------------------------------------------------------------------------
// Entry point
// ---------------------------------------------------------------------------
extern "C" void kernel_launch(void* const* d_in, const int* in_sizes, int n_in,
                              void* d_out, int out_size)
{
    const float* Q = (const float*)d_in[0];  // [32, 512, 512]
    const float* E = (const float*)d_in[1];  // [32, 2048, 512]
    float* O = (float*)d_out;                // [32, 512, 512]

    __nv_bfloat16 *Q2, *E2, *ET2;
    float* S;
    float2 *stat, *rowi;
    cudaGetSymbolAddress((void**)&Q2,   g_Q2);
    cudaGetSymbolAddress((void**)&E2,   g_E2);
    cudaGetSymbolAddress((void**)&S,    g_S);
    cudaGetSymbolAddress((void**)&ET2,  g_ET2);
    cudaGetSymbolAddress((void**)&stat, g_stat);
    cudaGetSymbolAddress((void**)&rowi, g_row);

    cudaFuncSetAttribute(gemm1_stats, cudaFuncAttributeMaxDynamicSharedMemorySize, GEMM_SMEM);
    cudaFuncSetAttribute(gemm2_fused, cudaFuncAttributeMaxDynamicSharedMemorySize, GEMM2_SMEM);

    // operand conversions
    split2_kernel<DIM><<<8192, 256>>>(Q, Q2, (long long)BATCH * TQ * DIM);
    esplit_kernel<<<dim3(TK / 32, DIM / 32, BATCH), dim3(32, 8)>>>(E, E2, ET2);

    // S = Q @ E^T  + per-tile softmax stats
    gemm1_stats<<<dim3(TK / 128, TQ / 128, BATCH), 256, GEMM_SMEM>>>(Q2, E2, S, stat);

    // merge tile stats -> per-row (max, 1/sum)
    rowstat_kernel<<<BATCH * TQ / 256, 256>>>(stat, rowi);

    // O = softmax(S) @ E  (fused exp/normalize/split in the A path)
    gemm2_fused<<<dim3(DIM / 128, TQ / 64, BATCH), 256, GEMM2_SMEM>>>(S, ET2, rowi, O);
}